// round 16
// baseline (speedup 1.0000x reference)
#include <cuda_runtime.h>
#include <cuda_fp16.h>
#include <math.h>
#include <stdint.h>

#define TOKENS 4096
#define HID    4096
#define NHEADS 32
#define NKVH   8
#define HDIM   128
#define SEQ    1024
#define QKV_LD 6144   // q(4096) | k(1024) | v(1024)
#define QK_LD  5120   // fp16 rope'd: q(4096) | k(1024)

// Scratch (__device__ globals; allocation-free rule)
__device__ float  g_qkv[TOKENS * QKV_LD];          // fp32 qkv (gemm out, rope/vt in)
__device__ __half g_xh[TOKENS * HID];              // x in fp16
__device__ __half g_wh[10240 * HID];               // wq|wk|wv|wo in fp16
__device__ __half g_attnh[TOKENS * HID];           // attention output in fp16
__device__ __half g_qkh[TOKENS * QK_LD];           // rope'd q|k in fp16
__device__ __half g_vt[4 * NKVH * HDIM * SEQ];     // V transposed [b][kvh][d][pos]
#define WQ_OFF 0
#define WK_OFF (4096 * 4096)
#define WV_OFF (WK_OFF + 1024 * 4096)
#define WO_OFF (WV_OFF + 1024 * 4096)

// ---------------------------------------------------------------------------
// Helpers
// ---------------------------------------------------------------------------
__device__ __forceinline__ uint32_t smem_u32(const void* p) {
    uint32_t a;
    asm("{ .reg .u64 t; cvta.to.shared.u64 t, %1; cvt.u32.u64 %0, t; }"
        : "=r"(a) : "l"(p));
    return a;
}
__device__ __forceinline__ void mma_f16(float c[4],
    unsigned a0, unsigned a1, unsigned a2, unsigned a3,
    unsigned b0, unsigned b1) {
    asm volatile(
        "mma.sync.aligned.m16n8k16.row.col.f32.f16.f16.f32 "
        "{%0,%1,%2,%3}, {%4,%5,%6,%7}, {%8,%9}, {%0,%1,%2,%3};"
        : "+f"(c[0]), "+f"(c[1]), "+f"(c[2]), "+f"(c[3])
        : "r"(a0), "r"(a1), "r"(a2), "r"(a3), "r"(b0), "r"(b1));
}
__device__ __forceinline__ void cp16(uint32_t d, const void* s) {
    asm volatile("cp.async.cg.shared.global [%0], [%1], 16;" :: "r"(d), "l"(s));
}
#define CP_COMMIT() asm volatile("cp.async.commit_group;" ::: "memory")
#define CP_WAIT1()  asm volatile("cp.async.wait_group 1;" ::: "memory")

// packed half2 exp2 — one MUFU op for two exps
__device__ __forceinline__ unsigned h2ex2(unsigned x) {
    unsigned r;
    asm("ex2.approx.f16x2 %0, %1;" : "=r"(r) : "r"(x));
    return r;
}

// ---------------------------------------------------------------------------
// fp32 -> fp16 convert (vectorized)
// ---------------------------------------------------------------------------
__global__ void conv_f2h(const float* __restrict__ s, __half* __restrict__ d,
                         int n4) {
    int i = blockIdx.x * blockDim.x + threadIdx.x;
    if (i >= n4) return;
    float4 v = *(const float4*)(s + i * 4);
    __half2* dp = (__half2*)(d + i * 4);
    dp[0] = __floats2half2_rn(v.x, v.y);
    dp[1] = __floats2half2_rn(v.z, v.w);
}

// ---------------------------------------------------------------------------
// FP16 GEMM v2: C[bm:bm+128, 0:128] = A @ Bt^T.
// 256 threads = 8 warps (2m x 4n), warp tile 64x32 (64 acc regs -> ~112
// regs/thread), 3-stage cp.async (60 KB), launch_bounds(256,2):
// 16 warps/SM = 4 warps/SMSP — doubles latency hiding vs round-11 config.
// Smem rows: 32 halves + 16B pad = 20 words (proven conflict-free class).
// ---------------------------------------------------------------------------
#define RSW   20
#define ASTB  (128 * RSW * 4)            // 10240 B per A stage
#define STGB  (2 * ASTB)                 // 20480 B per stage (A+B)
#define KTH   (HID / 32)                 // 128 iters
#define GSMEM (3 * STGB)                 // 61440 B

__device__ __forceinline__ void gemm128h(
    const __half* __restrict__ A, const __half* __restrict__ Bt,
    float* __restrict__ C, int ldc, int bm)
{
    extern __shared__ float smg[];

    const int tid  = threadIdx.x;
    const int wid  = tid >> 5;
    const int lane = tid & 31;
    const int g    = lane >> 2;
    const int t    = lane & 3;
    const int wm   = (wid & 1) * 64;      // 2 m-warps
    const int wn   = (wid >> 1) * 32;     // 4 n-warps
    const int lr   = tid >> 2;            // 0..63 load row base
    const int lc8  = (tid & 3) * 8;       // half offset in row

    const uint32_t sb   = smem_u32(smg);
    const uint32_t adst = sb + (uint32_t)(lr * 80 + (tid & 3) * 16);
    const uint32_t bdst = adst + (uint32_t)ASTB;

    const __half* a0p = A  + (size_t)(bm + lr) * HID + lc8;
    const __half* b0p = Bt + (size_t)lr * HID + lc8;

#define ISSUE(S, KI) do { \
    const __half* a_ = a0p + (size_t)(KI) * 32; \
    const __half* b_ = b0p + (size_t)(KI) * 32; \
    const uint32_t so_ = (uint32_t)(S) * (uint32_t)STGB; \
    cp16(adst + so_,         a_); \
    cp16(adst + so_ + 5120u, a_ + (size_t)64 * HID); \
    cp16(bdst + so_,         b_); \
    cp16(bdst + so_ + 5120u, b_ + (size_t)64 * HID); \
} while (0)

    float acc[4][4][4];
#pragma unroll
    for (int i = 0; i < 4; i++)
#pragma unroll
        for (int j = 0; j < 4; j++)
#pragma unroll
            for (int r = 0; r < 4; r++) acc[i][j][r] = 0.f;

    ISSUE(0, 0); CP_COMMIT();
    ISSUE(1, 1); CP_COMMIT();

    int s0 = 0, s2 = 2;
    for (int i = 0; i < KTH; i++) {
        CP_WAIT1();            // stage s0 complete (next tile may be pending)
        __syncthreads();

        if (i + 2 < KTH) ISSUE(s2, i + 2);
        CP_COMMIT();           // uniform group count

        const uint32_t* as = (const uint32_t*)smg + s0 * (STGB / 4);
        const uint32_t* bs = as + (ASTB / 4);
#pragma unroll
        for (int ks = 0; ks < 2; ks++) {
            const int kb = ks * 8;
            unsigned af[4][4], bf[4][2];
#pragma unroll
            for (int mi = 0; mi < 4; mi++) {
                const uint32_t* ap = as + (wm + mi * 16 + g) * RSW + kb + t;
                af[mi][0] = ap[0];
                af[mi][1] = ap[8 * RSW];
                af[mi][2] = ap[4];
                af[mi][3] = ap[8 * RSW + 4];
            }
#pragma unroll
            for (int ni = 0; ni < 4; ni++) {
                const uint32_t* bp = bs + (wn + ni * 8 + g) * RSW + kb + t;
                bf[ni][0] = bp[0];
                bf[ni][1] = bp[4];
            }
#pragma unroll
            for (int mi = 0; mi < 4; mi++)
#pragma unroll
                for (int ni = 0; ni < 4; ni++)
                    mma_f16(acc[mi][ni], af[mi][0], af[mi][1], af[mi][2], af[mi][3],
                            bf[ni][0], bf[ni][1]);
        }
        // rotate stages: s0 <- s0+1, s2 <- s2+1 (mod 3)
        s0 = (s0 == 2) ? 0 : s0 + 1;
        s2 = (s2 == 2) ? 0 : s2 + 1;
    }
#undef ISSUE

#pragma unroll
    for (int mi = 0; mi < 4; mi++) {
#pragma unroll
        for (int ni = 0; ni < 4; ni++) {
            float* cp = C + (size_t)(bm + wm + mi * 16 + g) * ldc + wn + ni * 8 + 2 * t;
            *(float2*)cp             = make_float2(acc[mi][ni][0], acc[mi][ni][1]);
            *(float2*)(cp + 8 * ldc) = make_float2(acc[mi][ni][2], acc[mi][ni][3]);
        }
    }
}

__global__ __launch_bounds__(256, 2)
void qkv_gemm(const __half* __restrict__ xh, const __half* __restrict__ wh,
              float* __restrict__ qkv) {
    const int nt = blockIdx.x;
    const __half* B;
    if (nt < 32)      B = wh + WQ_OFF + (size_t)nt * 128 * HID;
    else if (nt < 40) B = wh + WK_OFF + (size_t)(nt - 32) * 128 * HID;
    else              B = wh + WV_OFF + (size_t)(nt - 40) * 128 * HID;
    gemm128h(xh, B, qkv + nt * 128, QKV_LD, blockIdx.y * 128);
}

__global__ __launch_bounds__(256, 2)
void out_gemm(const __half* __restrict__ ah, const __half* __restrict__ wh,
              float* __restrict__ C) {
    gemm128h(ah, wh + WO_OFF + (size_t)blockIdx.x * 128 * HID,
             C + blockIdx.x * 128, HID, blockIdx.y * 128);
}

// ---------------------------------------------------------------------------
// RoPE: read fp32 q/k from g_qkv, write fp16 into packed g_qkh.
// ---------------------------------------------------------------------------
__global__ void rope_h(const float* __restrict__ qkv,
                       const int* __restrict__ positions,
                       __half* __restrict__ qkh) {
    int idx = blockIdx.x * blockDim.x + threadIdx.x;
    const int total = TOKENS * (NHEADS + NKVH) * 64;
    if (idx >= total) return;
    int d = idx & 63;
    int rest = idx >> 6;
    int head = rest % (NHEADS + NKVH);
    int t = rest / (NHEADS + NKVH);

    int pos = positions[t];
    pos = pos < 0 ? 0 : (pos > SEQ - 1 ? SEQ - 1 : pos);

    const int off = (head < NHEADS) ? head * HDIM : HID + (head - NHEADS) * HDIM;
    const float* src = qkv + (size_t)t * QKV_LD + off;
    __half* dst = qkh + (size_t)t * QK_LD + off;
    float x1 = src[d];
    float x2 = src[d + 64];

    const float LC = 0.14391156831212875f;   // ln(10000)/64
    int j1 = d >> 1;
    float f1 = expf(-(float)j1 * LC);
    float f2 = expf(-(float)(j1 + 32) * LC);
    float p = (float)pos;
    float s1, c1, s2, c2;
    sincosf(p * f1, &s1, &c1);
    sincosf(p * f2, &s2, &c2);

    dst[d]      = __float2half(x1 * c1 - x2 * s1);
    dst[d + 64] = __float2half(x2 * c2 + x1 * s2);
}

// ---------------------------------------------------------------------------
// V transpose+convert: g_qkv v-region [tok][d] fp32 -> g_vt [b][kvh][d][pos] fp16.
// ---------------------------------------------------------------------------
__global__ void conv_vt(const float* __restrict__ qkv, __half* __restrict__ vt) {
    __shared__ float tile[32][33];
    const int bk = blockIdx.z;               // b*8 + kvh
    const int p0 = blockIdx.x * 32;
    const int d0 = blockIdx.y * 32;
    const int tx = threadIdx.x & 31;
    const int ty = threadIdx.x >> 5;         // 0..7
    const int b  = bk >> 3, kvh = bk & 7;

    const float* src = qkv + (size_t)(b * SEQ + p0) * QKV_LD + 5120 + kvh * HDIM + d0;
#pragma unroll
    for (int i = 0; i < 4; i++) {
        int r = ty + 8 * i;                   // pos within tile
        tile[r][tx] = src[(size_t)r * QKV_LD + tx];
    }
    __syncthreads();
    __half* dst = vt + ((size_t)bk * HDIM + d0) * SEQ + p0;
#pragma unroll
    for (int i = 0; i < 4; i++) {
        int r = ty + 8 * i;                   // d within tile
        dst[(size_t)r * SEQ + tx] = __float2half(tile[tx][r]);
    }
}

// ---------------------------------------------------------------------------
// FP16 tensor-core flash attention (round-15 proven): XOR-swizzled pad-free
// smem, cp.async double-buffered K/V, log2-domain f16x2 softmax, 2 CTAs/SM.
// ---------------------------------------------------------------------------
#define QW64  64
#define KW64  64
#define VW32  32
#define PW32  32
#define Q_OFF 0
#define K_OFF (128 * QW64)                 // 8192
#define V_OFF (K_OFF + 2 * 64 * KW64)      // 16384
#define P_OFF (V_OFF + 2 * 128 * VW32)     // 24576
#define ATTW  (P_OFF + 128 * PW32)         // 28672 words
#define ATT_SMEM (ATTW * 4)                // 114688 B

__global__ __launch_bounds__(256, 2)
void attn_h(const __half* __restrict__ qkh, const __half* __restrict__ vt,
            __half* __restrict__ aout) {
    extern __shared__ uint32_t smw[];
    uint32_t* Qs = smw + Q_OFF;
    uint32_t* Ks = smw + K_OFF;
    uint32_t* Vs = smw + V_OFF;
    uint32_t* Ps = smw + P_OFF;

    const int qb = 7 - blockIdx.x;         // long CTAs first
    const int h  = blockIdx.y;
    const int b  = blockIdx.z;
    const int kvh = h >> 2;
    const int tid = threadIdx.x;
    const int wid = tid >> 5;
    const int lane = tid & 31;
    const int g = lane >> 2;
    const int t = lane & 3;
    const int swg = g << 2;
    const int wm = wid * 16;
    const int q0 = qb * 128;
    const size_t tok0 = (size_t)b * SEQ;

    const __half* qbase = qkh + (tok0 + q0) * QK_LD + h * HDIM;
    const __half* kbase = qkh + tok0 * QK_LD + HID + kvh * HDIM;
    const __half* vtb   = vt + (size_t)(b * NKVH + kvh) * HDIM * SEQ;
    const int nkb = 2 * (qb + 1);

    const uint32_t sb = smem_u32(smw);

#define ISSUE_KV(S, KB) do { \
    const int k0_ = (KB) * 64; \
    const uint32_t kb_ = sb + (uint32_t)(K_OFF + (S) * 4096) * 4u; \
    const uint32_t vb_ = sb + (uint32_t)(V_OFF + (S) * 4096) * 4u; \
    _Pragma("unroll") \
    for (int i_ = 0; i_ < 4; i_++) { \
        int u_ = tid + 256 * i_; \
        int r_ = u_ >> 4, c4_ = (u_ & 15) * 4; \
        cp16(kb_ + (uint32_t)(r_ * KW64 + (c4_ ^ ((r_ & 7) << 2))) * 4u, \
             kbase + (size_t)(k0_ + r_) * QK_LD + c4_ * 2); \
    } \
    _Pragma("unroll") \
    for (int i_ = 0; i_ < 4; i_++) { \
        int u_ = tid + 256 * i_; \
        int r_ = u_ >> 3, c4_ = (u_ & 7) * 4; \
        cp16(vb_ + (uint32_t)(r_ * VW32 + (c4_ ^ ((r_ & 7) << 2))) * 4u, \
             vtb + (size_t)r_ * SEQ + k0_ + c4_ * 2); \
    } \
} while (0)

    ISSUE_KV(0, 0); CP_COMMIT();
    ISSUE_KV(1, 1); CP_COMMIT();

    for (int u = tid; u < 128 * 16; u += 256) {
        int r = u >> 4, c4 = (u & 15) * 4;
        *(uint4*)(Qs + r * QW64 + (c4 ^ ((r & 7) << 2))) =
            *(const uint4*)(qbase + (size_t)r * QK_LD + c4 * 2);
    }

    float m[2], l[2], o[16][4];
    m[0] = m[1] = -INFINITY;
    l[0] = l[1] = 0.f;
#pragma unroll
    for (int nj = 0; nj < 16; nj++)
#pragma unroll
        for (int r = 0; r < 4; r++) o[nj][r] = 0.f;

    for (int kb = 0; kb < nkb; kb++) {
        const int k0 = kb * 64;
        CP_WAIT1();
        __syncthreads();

        if (k0 <= q0 + wm + 15) {
            const uint32_t* Kb = Ks + (kb & 1) * 4096;
            const uint32_t* Vb = Vs + (kb & 1) * 4096;

            float s[8][4];
#pragma unroll
            for (int ni = 0; ni < 8; ni++)
#pragma unroll
                for (int r = 0; r < 4; r++) s[ni][r] = 0.f;

#pragma unroll
            for (int kk = 0; kk < 8; kk++) {
                const int col = (kk * 8 + t) ^ swg;
                const int qi = (wm + g) * QW64 + col;
                unsigned a0 = Qs[qi],      a1 = Qs[qi + 8 * QW64];
                unsigned a2 = Qs[qi ^ 4],  a3 = Qs[(qi ^ 4) + 8 * QW64];
#pragma unroll
                for (int ni = 0; ni < 8; ni++) {
                    const int ki = (ni * 8 + g) * KW64 + col;
                    mma_f16(s[ni], a0, a1, a2, a3, Kb[ki], Kb[ki ^ 4]);
                }
            }

            const float sc2 = 0.12751742770800936f;  // log2(e)/sqrt(128)
#pragma unroll
            for (int h2 = 0; h2 < 2; h2++) {
                const int qpos = q0 + wm + g + h2 * 8;
                float rowm = -INFINITY;
#pragma unroll
                for (int ni = 0; ni < 8; ni++) {
#pragma unroll
                    for (int cj = 0; cj < 2; cj++) {
                        float v = s[ni][h2 * 2 + cj] * sc2;
                        if (k0 + ni * 8 + 2 * t + cj > qpos) v = -INFINITY;
                        s[ni][h2 * 2 + cj] = v;
                        rowm = fmaxf(rowm, v);
                    }
                }
                rowm = fmaxf(rowm, __shfl_xor_sync(0xffffffffu, rowm, 1));
                rowm = fmaxf(rowm, __shfl_xor_sync(0xffffffffu, rowm, 2));
                float nm  = fmaxf(m[h2], rowm);
                float nm2 = (nm == -INFINITY) ? 0.f : nm;    // NaN guard
                float corr = exp2f(m[h2] - nm2);
                float rs = 0.f;
                const int prow = (wm + g + h2 * 8) * PW32;
#pragma unroll
                for (int ni = 0; ni < 8; ni++) {
                    __half2 qh = __floats2half2_rn(s[ni][h2 * 2]     - nm2,
                                                   s[ni][h2 * 2 + 1] - nm2);
                    unsigned ph = h2ex2(*(unsigned*)&qh);
                    Ps[prow + ((ni * 4 + t) ^ swg)] = ph;
                    float2 pf = __half22float2(*(__half2*)&ph);
                    rs += pf.x + pf.y;
                }
                rs += __shfl_xor_sync(0xffffffffu, rs, 1);
                rs += __shfl_xor_sync(0xffffffffu, rs, 2);
                l[h2] = l[h2] * corr + rs;
                m[h2] = nm;
#pragma unroll
                for (int nj = 0; nj < 16; nj++) {
                    o[nj][h2 * 2]     *= corr;
                    o[nj][h2 * 2 + 1] *= corr;
                }
            }
            __syncwarp();

#pragma unroll
            for (int kk = 0; kk < 4; kk++) {
                const int col = (kk * 8 + t) ^ swg;
                const int pi = (wm + g) * PW32 + col;
                unsigned a0 = Ps[pi],      a1 = Ps[pi + 8 * PW32];
                unsigned a2 = Ps[pi ^ 4],  a3 = Ps[(pi ^ 4) + 8 * PW32];
#pragma unroll
                for (int nj = 0; nj < 16; nj++) {
                    const int vi = (nj * 8 + g) * VW32 + col;
                    mma_f16(o[nj], a0, a1, a2, a3, Vb[vi], Vb[vi ^ 4]);
                }
            }
        }

        __syncthreads();
        if (kb + 2 < nkb) ISSUE_KV(kb & 1, kb + 2);
        CP_COMMIT();
    }
#undef ISSUE_KV

    __half* ob = aout + (tok0 + q0) * HID + h * HDIM;
#pragma unroll
    for (int h2 = 0; h2 < 2; h2++) {
        const float inv = 1.0f / l[h2];
        const int row = wm + g + h2 * 8;
#pragma unroll
        for (int nj = 0; nj < 16; nj++) {
            *(__half2*)(ob + (size_t)row * HID + nj * 8 + 2 * t) =
                __floats2half2_rn(o[nj][h2 * 2] * inv, o[nj][h2 * 2 + 1] * inv);
        }
    }
}

// ---------------------------------------------------------------------------
// Launch
// ---------------------------------------------------------------------------
extern "C" void kernel_launch(void* const* d_in, const int* in_sizes, int n_in,
                              void* d_out, int out_size) {
    const float* x         = (const float*)d_in[0];
    const int*   positions = (const int*)d_in[1];
    const float* wq        = (const float*)d_in[3];
    const float* wk        = (const float*)d_in[4];
    const float* wv        = (const float*)d_in[5];
    const float* wo        = (const float*)d_in[6];
    float* out = (float*)d_out;

    float  *qkv = nullptr;
    __half *xh = nullptr, *wh = nullptr, *attnh = nullptr, *qkh = nullptr, *vt = nullptr;
    cudaGetSymbolAddress((void**)&qkv,   g_qkv);
    cudaGetSymbolAddress((void**)&xh,    g_xh);
    cudaGetSymbolAddress((void**)&wh,    g_wh);
    cudaGetSymbolAddress((void**)&attnh, g_attnh);
    cudaGetSymbolAddress((void**)&qkh,   g_qkh);
    cudaGetSymbolAddress((void**)&vt,    g_vt);

    cudaFuncSetAttribute(qkv_gemm, cudaFuncAttributeMaxDynamicSharedMemorySize, GSMEM);
    cudaFuncSetAttribute(out_gemm, cudaFuncAttributeMaxDynamicSharedMemorySize, GSMEM);
    cudaFuncSetAttribute(attn_h,   cudaFuncAttributeMaxDynamicSharedMemorySize, ATT_SMEM);

    // fp32 -> fp16 converts (x + weights)
    const int cb = 256;
    conv_f2h<<<(TOKENS * HID / 4 + cb - 1) / cb, cb>>>(x,  xh,          TOKENS * HID / 4);
    conv_f2h<<<(4096 * HID / 4 + cb - 1) / cb, cb>>>(wq, wh + WQ_OFF, 4096 * HID / 4);
    conv_f2h<<<(1024 * HID / 4 + cb - 1) / cb, cb>>>(wk, wh + WK_OFF, 1024 * HID / 4);
    conv_f2h<<<(1024 * HID / 4 + cb - 1) / cb, cb>>>(wv, wh + WV_OFF, 1024 * HID / 4);
    conv_f2h<<<(4096 * HID / 4 + cb - 1) / cb, cb>>>(wo, wh + WO_OFF, 4096 * HID / 4);

    // QKV projection (fp16 HMMA, 256 thr, 4 warps/SMSP)
    qkv_gemm<<<dim3(48, 32), 256, GSMEM>>>(xh, wh, qkv);

    // RoPE -> fp16 q|k; V transpose -> fp16 [d][pos]
    rope_h<<<(TOKENS * 40 * 64 + 255) / 256, 256>>>(qkv, positions, qkh);
    conv_vt<<<dim3(SEQ / 32, HDIM / 32, 4 * NKVH), 256>>>(qkv, vt);

    // Flash attention (fp16 HMMA, cp.async K/V pipeline, 2 CTAs/SM)
    attn_h<<<dim3(SEQ / 128, NHEADS, TOKENS / SEQ), 256, ATT_SMEM>>>(qkh, vt, attnh);

    // Output projection (fp16 HMMA, 256 thr, 4 warps/SMSP)
    out_gemm<<<dim3(32, 32), 256, GSMEM>>>(attnh, wh, out);
}

// round 17
// speedup vs baseline: 1.2385x; 1.2385x over previous
#include <cuda_runtime.h>
#include <cuda_fp16.h>
#include <math.h>
#include <stdint.h>

#define TOKENS 4096
#define HID    4096
#define NHEADS 32
#define NKVH   8
#define HDIM   128
#define SEQ    1024
#define QKV_LD 6144   // q(4096) | k(1024) | v(1024)
#define QK_LD  5120   // fp16 rope'd: q(4096) | k(1024)

// Scratch (__device__ globals; allocation-free rule)
__device__ float  g_qkv[TOKENS * QKV_LD];          // fp32 qkv (gemm out, rope/vt in)
__device__ __half g_xh[TOKENS * HID];              // x in fp16
__device__ __half g_wh[10240 * HID];               // wq|wk|wv|wo in fp16
__device__ __half g_attnh[TOKENS * HID];           // attention output in fp16
__device__ __half g_qkh[TOKENS * QK_LD];           // rope'd q|k in fp16
__device__ __half g_vt[4 * NKVH * HDIM * SEQ];     // V transposed [b][kvh][d][pos]
#define WQ_OFF 0
#define WK_OFF (4096 * 4096)
#define WV_OFF (WK_OFF + 1024 * 4096)
#define WO_OFF (WV_OFF + 1024 * 4096)

// ---------------------------------------------------------------------------
// Helpers
// ---------------------------------------------------------------------------
__device__ __forceinline__ uint32_t smem_u32(const void* p) {
    uint32_t a;
    asm("{ .reg .u64 t; cvta.to.shared.u64 t, %1; cvt.u32.u64 %0, t; }"
        : "=r"(a) : "l"(p));
    return a;
}
__device__ __forceinline__ void mma_f16(float c[4],
    unsigned a0, unsigned a1, unsigned a2, unsigned a3,
    unsigned b0, unsigned b1) {
    asm volatile(
        "mma.sync.aligned.m16n8k16.row.col.f32.f16.f16.f32 "
        "{%0,%1,%2,%3}, {%4,%5,%6,%7}, {%8,%9}, {%0,%1,%2,%3};"
        : "+f"(c[0]), "+f"(c[1]), "+f"(c[2]), "+f"(c[3])
        : "r"(a0), "r"(a1), "r"(a2), "r"(a3), "r"(b0), "r"(b1));
}
__device__ __forceinline__ void ldsm4(unsigned& r0, unsigned& r1,
                                      unsigned& r2, unsigned& r3, uint32_t a) {
    asm volatile("ldmatrix.sync.aligned.m8n8.x4.shared.b16 {%0,%1,%2,%3}, [%4];"
        : "=r"(r0), "=r"(r1), "=r"(r2), "=r"(r3) : "r"(a));
}
__device__ __forceinline__ void cp16(uint32_t d, const void* s) {
    asm volatile("cp.async.cg.shared.global [%0], [%1], 16;" :: "r"(d), "l"(s));
}
#define CP_COMMIT() asm volatile("cp.async.commit_group;" ::: "memory")
#define CP_WAIT2()  asm volatile("cp.async.wait_group 2;" ::: "memory")
#define CP_WAIT1()  asm volatile("cp.async.wait_group 1;" ::: "memory")

// packed half2 exp2 — one MUFU op for two exps
__device__ __forceinline__ unsigned h2ex2(unsigned x) {
    unsigned r;
    asm("ex2.approx.f16x2 %0, %1;" : "=r"(r) : "r"(x));
    return r;
}

// ---------------------------------------------------------------------------
// fp32 -> fp16 convert (vectorized)
// ---------------------------------------------------------------------------
__global__ void conv_f2h(const float* __restrict__ s, __half* __restrict__ d,
                         int n4) {
    int i = blockIdx.x * blockDim.x + threadIdx.x;
    if (i >= n4) return;
    float4 v = *(const float4*)(s + i * 4);
    __half2* dp = (__half2*)(d + i * 4);
    dp[0] = __floats2half2_rn(v.x, v.y);
    dp[1] = __floats2half2_rn(v.z, v.w);
}

// ---------------------------------------------------------------------------
// FP16 GEMM (round-15 proven config + ldmatrix fragment loads):
// C[bm:bm+128, 0:128] = A @ Bt^T. 128 threads = 4 warps (2m x 2n),
// warp tile 64x64, 4-stage cp.async, 80 KB smem, 2 CTAs/SM.
// ldmatrix.x4 replaces 96 scalar LDS/iter with 16 instructions; lane->row
// mapping verified identical to the proven scalar gathers; 8-row phases at
// stride-20 words tile all 32 banks (conflict-free).
// ---------------------------------------------------------------------------
#define RSW   20
#define ASTB  (128 * RSW * 4)            // 10240
#define STGB  (2 * ASTB)                 // 20480
#define KTH   (HID / 32)                 // 128
#define GSMEM (4 * STGB)                 // 81920

__device__ __forceinline__ void gemm128h(
    const __half* __restrict__ A, const __half* __restrict__ Bt,
    float* __restrict__ C, int ldc, int bm)
{
    extern __shared__ float smg[];

    const int tid  = threadIdx.x;
    const int wid  = tid >> 5;
    const int lane = tid & 31;
    const int g    = lane >> 2;
    const int t    = lane & 3;
    const int wm   = (wid & 1) * 64;
    const int wn   = (wid >> 1) * 64;
    const int lr   = tid >> 2;
    const int lc8  = (tid & 3) * 8;

    const uint32_t sb   = smem_u32(smg);
    const uint32_t adst = sb + (uint32_t)(lr * 80 + (tid & 3) * 16);
    const uint32_t bdst = adst + (uint32_t)ASTB;

    // ldmatrix per-lane source addresses (stage 0, tile 0, k-slab 0)
    // A groups: rows0-7@k0 | rows8-15@k0 | rows0-7@+16B | rows8-15@+16B
    const int arow = (lane & 7) + ((lane >> 3) & 1) * 8;
    const int acolw = (lane >> 4) * 4;
    // B pair groups: n0-7@k0 | n0-7@+16B | n8-15@k0 | n8-15@+16B
    const int brow = (lane & 7) + (lane >> 4) * 8;
    const int bcolw = ((lane >> 3) & 1) * 4;
    const uint32_t asrc0 = sb + (uint32_t)(((wm + arow) * RSW + acolw) * 4);
    const uint32_t bsrc0 = sb + (uint32_t)ASTB +
                           (uint32_t)(((wn + brow) * RSW + bcolw) * 4);

    const __half* a0p = A  + (size_t)(bm + lr) * HID + lc8;
    const __half* b0p = Bt + (size_t)lr * HID + lc8;

#define ISSUE(S, KI) do { \
    const __half* a_ = a0p + (size_t)(KI) * 32; \
    const __half* b_ = b0p + (size_t)(KI) * 32; \
    const uint32_t so_ = (uint32_t)(S) * (uint32_t)STGB; \
    cp16(adst + so_,         a_); \
    cp16(adst + so_ + 2560u, a_ + (size_t)32 * HID); \
    cp16(adst + so_ + 5120u, a_ + (size_t)64 * HID); \
    cp16(adst + so_ + 7680u, a_ + (size_t)96 * HID); \
    cp16(bdst + so_,         b_); \
    cp16(bdst + so_ + 2560u, b_ + (size_t)32 * HID); \
    cp16(bdst + so_ + 5120u, b_ + (size_t)64 * HID); \
    cp16(bdst + so_ + 7680u, b_ + (size_t)96 * HID); \
} while (0)

    float acc[4][8][4];
#pragma unroll
    for (int i = 0; i < 4; i++)
#pragma unroll
        for (int j = 0; j < 8; j++)
#pragma unroll
            for (int r = 0; r < 4; r++) acc[i][j][r] = 0.f;

    ISSUE(0, 0); CP_COMMIT();
    ISSUE(1, 1); CP_COMMIT();
    ISSUE(2, 2); CP_COMMIT();

    for (int i = 0; i < KTH; i++) {
        CP_WAIT2();
        __syncthreads();

        if (i + 3 < KTH) ISSUE((i + 3) & 3, i + 3);
        CP_COMMIT();

        const uint32_t soff = (uint32_t)(i & 3) * (uint32_t)STGB;
#pragma unroll
        for (int ks = 0; ks < 2; ks++) {
            const uint32_t ko = soff + (uint32_t)ks * 32u;   // kb*4 bytes
            unsigned af[4][4], bf[8][2];
#pragma unroll
            for (int mi = 0; mi < 4; mi++)
                ldsm4(af[mi][0], af[mi][1], af[mi][2], af[mi][3],
                      asrc0 + ko + (uint32_t)(mi * 16 * RSW * 4));
#pragma unroll
            for (int pr = 0; pr < 4; pr++)
                ldsm4(bf[2 * pr][0], bf[2 * pr][1],
                      bf[2 * pr + 1][0], bf[2 * pr + 1][1],
                      bsrc0 + ko + (uint32_t)(pr * 16 * RSW * 4));
#pragma unroll
            for (int mi = 0; mi < 4; mi++)
#pragma unroll
                for (int ni = 0; ni < 8; ni++)
                    mma_f16(acc[mi][ni], af[mi][0], af[mi][1], af[mi][2], af[mi][3],
                            bf[ni][0], bf[ni][1]);
        }
    }
#undef ISSUE

#pragma unroll
    for (int mi = 0; mi < 4; mi++) {
#pragma unroll
        for (int ni = 0; ni < 8; ni++) {
            float* cp = C + (size_t)(bm + wm + mi * 16 + g) * ldc + wn + ni * 8 + 2 * t;
            *(float2*)cp             = make_float2(acc[mi][ni][0], acc[mi][ni][1]);
            *(float2*)(cp + 8 * ldc) = make_float2(acc[mi][ni][2], acc[mi][ni][3]);
        }
    }
}

__global__ __launch_bounds__(128, 2)
void qkv_gemm(const __half* __restrict__ xh, const __half* __restrict__ wh,
              float* __restrict__ qkv) {
    const int nt = blockIdx.x;
    const __half* B;
    if (nt < 32)      B = wh + WQ_OFF + (size_t)nt * 128 * HID;
    else if (nt < 40) B = wh + WK_OFF + (size_t)(nt - 32) * 128 * HID;
    else              B = wh + WV_OFF + (size_t)(nt - 40) * 128 * HID;
    gemm128h(xh, B, qkv + nt * 128, QKV_LD, blockIdx.y * 128);
}

__global__ __launch_bounds__(128, 2)
void out_gemm(const __half* __restrict__ ah, const __half* __restrict__ wh,
              float* __restrict__ C) {
    gemm128h(ah, wh + WO_OFF + (size_t)blockIdx.x * 128 * HID,
             C + blockIdx.x * 128, HID, blockIdx.y * 128);
}

// ---------------------------------------------------------------------------
// RoPE: read fp32 q/k from g_qkv, write fp16 into packed g_qkh.
// ---------------------------------------------------------------------------
__global__ void rope_h(const float* __restrict__ qkv,
                       const int* __restrict__ positions,
                       __half* __restrict__ qkh) {
    int idx = blockIdx.x * blockDim.x + threadIdx.x;
    const int total = TOKENS * (NHEADS + NKVH) * 64;
    if (idx >= total) return;
    int d = idx & 63;
    int rest = idx >> 6;
    int head = rest % (NHEADS + NKVH);
    int t = rest / (NHEADS + NKVH);

    int pos = positions[t];
    pos = pos < 0 ? 0 : (pos > SEQ - 1 ? SEQ - 1 : pos);

    const int off = (head < NHEADS) ? head * HDIM : HID + (head - NHEADS) * HDIM;
    const float* src = qkv + (size_t)t * QKV_LD + off;
    __half* dst = qkh + (size_t)t * QK_LD + off;
    float x1 = src[d];
    float x2 = src[d + 64];

    const float LC = 0.14391156831212875f;   // ln(10000)/64
    int j1 = d >> 1;
    float f1 = expf(-(float)j1 * LC);
    float f2 = expf(-(float)(j1 + 32) * LC);
    float p = (float)pos;
    float s1, c1, s2, c2;
    sincosf(p * f1, &s1, &c1);
    sincosf(p * f2, &s2, &c2);

    dst[d]      = __float2half(x1 * c1 - x2 * s1);
    dst[d + 64] = __float2half(x2 * c2 + x1 * s2);
}

// ---------------------------------------------------------------------------
// V transpose+convert: g_qkv v-region [tok][d] fp32 -> g_vt [b][kvh][d][pos] fp16.
// ---------------------------------------------------------------------------
__global__ void conv_vt(const float* __restrict__ qkv, __half* __restrict__ vt) {
    __shared__ float tile[32][33];
    const int bk = blockIdx.z;               // b*8 + kvh
    const int p0 = blockIdx.x * 32;
    const int d0 = blockIdx.y * 32;
    const int tx = threadIdx.x & 31;
    const int ty = threadIdx.x >> 5;         // 0..7
    const int b  = bk >> 3, kvh = bk & 7;

    const float* src = qkv + (size_t)(b * SEQ + p0) * QKV_LD + 5120 + kvh * HDIM + d0;
#pragma unroll
    for (int i = 0; i < 4; i++) {
        int r = ty + 8 * i;                   // pos within tile
        tile[r][tx] = src[(size_t)r * QKV_LD + tx];
    }
    __syncthreads();
    __half* dst = vt + ((size_t)bk * HDIM + d0) * SEQ + p0;
#pragma unroll
    for (int i = 0; i < 4; i++) {
        int r = ty + 8 * i;                   // d within tile
        dst[(size_t)r * SEQ + tx] = __float2half(tile[tx][r]);
    }
}

// ---------------------------------------------------------------------------
// FP16 tensor-core flash attention (round-15 proven): XOR-swizzled pad-free
// smem, cp.async double-buffered K/V, log2-domain f16x2 softmax, 2 CTAs/SM.
// ---------------------------------------------------------------------------
#define QW64  64
#define KW64  64
#define VW32  32
#define PW32  32
#define Q_OFF 0
#define K_OFF (128 * QW64)                 // 8192
#define V_OFF (K_OFF + 2 * 64 * KW64)      // 16384
#define P_OFF (V_OFF + 2 * 128 * VW32)     // 24576
#define ATTW  (P_OFF + 128 * PW32)         // 28672 words
#define ATT_SMEM (ATTW * 4)                // 114688 B

__global__ __launch_bounds__(256, 2)
void attn_h(const __half* __restrict__ qkh, const __half* __restrict__ vt,
            __half* __restrict__ aout) {
    extern __shared__ uint32_t smw[];
    uint32_t* Qs = smw + Q_OFF;
    uint32_t* Ks = smw + K_OFF;
    uint32_t* Vs = smw + V_OFF;
    uint32_t* Ps = smw + P_OFF;

    const int qb = 7 - blockIdx.x;         // long CTAs first
    const int h  = blockIdx.y;
    const int b  = blockIdx.z;
    const int kvh = h >> 2;
    const int tid = threadIdx.x;
    const int wid = tid >> 5;
    const int lane = tid & 31;
    const int g = lane >> 2;
    const int t = lane & 3;
    const int swg = g << 2;
    const int wm = wid * 16;
    const int q0 = qb * 128;
    const size_t tok0 = (size_t)b * SEQ;

    const __half* qbase = qkh + (tok0 + q0) * QK_LD + h * HDIM;
    const __half* kbase = qkh + tok0 * QK_LD + HID + kvh * HDIM;
    const __half* vtb   = vt + (size_t)(b * NKVH + kvh) * HDIM * SEQ;
    const int nkb = 2 * (qb + 1);

    const uint32_t sb = smem_u32(smw);

#define ISSUE_KV(S, KB) do { \
    const int k0_ = (KB) * 64; \
    const uint32_t kb_ = sb + (uint32_t)(K_OFF + (S) * 4096) * 4u; \
    const uint32_t vb_ = sb + (uint32_t)(V_OFF + (S) * 4096) * 4u; \
    _Pragma("unroll") \
    for (int i_ = 0; i_ < 4; i_++) { \
        int u_ = tid + 256 * i_; \
        int r_ = u_ >> 4, c4_ = (u_ & 15) * 4; \
        cp16(kb_ + (uint32_t)(r_ * KW64 + (c4_ ^ ((r_ & 7) << 2))) * 4u, \
             kbase + (size_t)(k0_ + r_) * QK_LD + c4_ * 2); \
    } \
    _Pragma("unroll") \
    for (int i_ = 0; i_ < 4; i_++) { \
        int u_ = tid + 256 * i_; \
        int r_ = u_ >> 3, c4_ = (u_ & 7) * 4; \
        cp16(vb_ + (uint32_t)(r_ * VW32 + (c4_ ^ ((r_ & 7) << 2))) * 4u, \
             vtb + (size_t)r_ * SEQ + k0_ + c4_ * 2); \
    } \
} while (0)

    ISSUE_KV(0, 0); CP_COMMIT();
    ISSUE_KV(1, 1); CP_COMMIT();

    for (int u = tid; u < 128 * 16; u += 256) {
        int r = u >> 4, c4 = (u & 15) * 4;
        *(uint4*)(Qs + r * QW64 + (c4 ^ ((r & 7) << 2))) =
            *(const uint4*)(qbase + (size_t)r * QK_LD + c4 * 2);
    }

    float m[2], l[2], o[16][4];
    m[0] = m[1] = -INFINITY;
    l[0] = l[1] = 0.f;
#pragma unroll
    for (int nj = 0; nj < 16; nj++)
#pragma unroll
        for (int r = 0; r < 4; r++) o[nj][r] = 0.f;

    for (int kb = 0; kb < nkb; kb++) {
        const int k0 = kb * 64;
        CP_WAIT1();
        __syncthreads();

        if (k0 <= q0 + wm + 15) {
            const uint32_t* Kb = Ks + (kb & 1) * 4096;
            const uint32_t* Vb = Vs + (kb & 1) * 4096;

            float s[8][4];
#pragma unroll
            for (int ni = 0; ni < 8; ni++)
#pragma unroll
                for (int r = 0; r < 4; r++) s[ni][r] = 0.f;

#pragma unroll
            for (int kk = 0; kk < 8; kk++) {
                const int col = (kk * 8 + t) ^ swg;
                const int qi = (wm + g) * QW64 + col;
                unsigned a0 = Qs[qi],      a1 = Qs[qi + 8 * QW64];
                unsigned a2 = Qs[qi ^ 4],  a3 = Qs[(qi ^ 4) + 8 * QW64];
#pragma unroll
                for (int ni = 0; ni < 8; ni++) {
                    const int ki = (ni * 8 + g) * KW64 + col;
                    mma_f16(s[ni], a0, a1, a2, a3, Kb[ki], Kb[ki ^ 4]);
                }
            }

            const float sc2 = 0.12751742770800936f;  // log2(e)/sqrt(128)
#pragma unroll
            for (int h2 = 0; h2 < 2; h2++) {
                const int qpos = q0 + wm + g + h2 * 8;
                float rowm = -INFINITY;
#pragma unroll
                for (int ni = 0; ni < 8; ni++) {
#pragma unroll
                    for (int cj = 0; cj < 2; cj++) {
                        float v = s[ni][h2 * 2 + cj] * sc2;
                        if (k0 + ni * 8 + 2 * t + cj > qpos) v = -INFINITY;
                        s[ni][h2 * 2 + cj] = v;
                        rowm = fmaxf(rowm, v);
                    }
                }
                rowm = fmaxf(rowm, __shfl_xor_sync(0xffffffffu, rowm, 1));
                rowm = fmaxf(rowm, __shfl_xor_sync(0xffffffffu, rowm, 2));
                float nm  = fmaxf(m[h2], rowm);
                float nm2 = (nm == -INFINITY) ? 0.f : nm;    // NaN guard
                float corr = exp2f(m[h2] - nm2);
                float rs = 0.f;
                const int prow = (wm + g + h2 * 8) * PW32;
#pragma unroll
                for (int ni = 0; ni < 8; ni++) {
                    __half2 qh = __floats2half2_rn(s[ni][h2 * 2]     - nm2,
                                                   s[ni][h2 * 2 + 1] - nm2);
                    unsigned ph = h2ex2(*(unsigned*)&qh);
                    Ps[prow + ((ni * 4 + t) ^ swg)] = ph;
                    float2 pf = __half22float2(*(__half2*)&ph);
                    rs += pf.x + pf.y;
                }
                rs += __shfl_xor_sync(0xffffffffu, rs, 1);
                rs += __shfl_xor_sync(0xffffffffu, rs, 2);
                l[h2] = l[h2] * corr + rs;
                m[h2] = nm;
#pragma unroll
                for (int nj = 0; nj < 16; nj++) {
                    o[nj][h2 * 2]     *= corr;
                    o[nj][h2 * 2 + 1] *= corr;
                }
            }
            __syncwarp();

#pragma unroll
            for (int kk = 0; kk < 4; kk++) {
                const int col = (kk * 8 + t) ^ swg;
                const int pi = (wm + g) * PW32 + col;
                unsigned a0 = Ps[pi],      a1 = Ps[pi + 8 * PW32];
                unsigned a2 = Ps[pi ^ 4],  a3 = Ps[(pi ^ 4) + 8 * PW32];
#pragma unroll
                for (int nj = 0; nj < 16; nj++) {
                    const int vi = (nj * 8 + g) * VW32 + col;
                    mma_f16(o[nj], a0, a1, a2, a3, Vb[vi], Vb[vi ^ 4]);
                }
            }
        }

        __syncthreads();
        if (kb + 2 < nkb) ISSUE_KV(kb & 1, kb + 2);
        CP_COMMIT();
    }
#undef ISSUE_KV

    __half* ob = aout + (tok0 + q0) * HID + h * HDIM;
#pragma unroll
    for (int h2 = 0; h2 < 2; h2++) {
        const float inv = 1.0f / l[h2];
        const int row = wm + g + h2 * 8;
#pragma unroll
        for (int nj = 0; nj < 16; nj++) {
            *(__half2*)(ob + (size_t)row * HID + nj * 8 + 2 * t) =
                __floats2half2_rn(o[nj][h2 * 2] * inv, o[nj][h2 * 2 + 1] * inv);
        }
    }
}

// ---------------------------------------------------------------------------
// Launch
// ---------------------------------------------------------------------------
extern "C" void kernel_launch(void* const* d_in, const int* in_sizes, int n_in,
                              void* d_out, int out_size) {
    const float* x         = (const float*)d_in[0];
    const int*   positions = (const int*)d_in[1];
    const float* wq        = (const float*)d_in[3];
    const float* wk        = (const float*)d_in[4];
    const float* wv        = (const float*)d_in[5];
    const float* wo        = (const float*)d_in[6];
    float* out = (float*)d_out;

    float  *qkv = nullptr;
    __half *xh = nullptr, *wh = nullptr, *attnh = nullptr, *qkh = nullptr, *vt = nullptr;
    cudaGetSymbolAddress((void**)&qkv,   g_qkv);
    cudaGetSymbolAddress((void**)&xh,    g_xh);
    cudaGetSymbolAddress((void**)&wh,    g_wh);
    cudaGetSymbolAddress((void**)&attnh, g_attnh);
    cudaGetSymbolAddress((void**)&qkh,   g_qkh);
    cudaGetSymbolAddress((void**)&vt,    g_vt);

    cudaFuncSetAttribute(qkv_gemm, cudaFuncAttributeMaxDynamicSharedMemorySize, GSMEM);
    cudaFuncSetAttribute(out_gemm, cudaFuncAttributeMaxDynamicSharedMemorySize, GSMEM);
    cudaFuncSetAttribute(attn_h,   cudaFuncAttributeMaxDynamicSharedMemorySize, ATT_SMEM);

    // fp32 -> fp16 converts (x + weights)
    const int cb = 256;
    conv_f2h<<<(TOKENS * HID / 4 + cb - 1) / cb, cb>>>(x,  xh,          TOKENS * HID / 4);
    conv_f2h<<<(4096 * HID / 4 + cb - 1) / cb, cb>>>(wq, wh + WQ_OFF, 4096 * HID / 4);
    conv_f2h<<<(1024 * HID / 4 + cb - 1) / cb, cb>>>(wk, wh + WK_OFF, 1024 * HID / 4);
    conv_f2h<<<(1024 * HID / 4 + cb - 1) / cb, cb>>>(wv, wh + WV_OFF, 1024 * HID / 4);
    conv_f2h<<<(4096 * HID / 4 + cb - 1) / cb, cb>>>(wo, wh + WO_OFF, 4096 * HID / 4);

    // QKV projection (fp16 HMMA + ldmatrix)
    qkv_gemm<<<dim3(48, 32), 128, GSMEM>>>(xh, wh, qkv);

    // RoPE -> fp16 q|k; V transpose -> fp16 [d][pos]
    rope_h<<<(TOKENS * 40 * 64 + 255) / 256, 256>>>(qkv, positions, qkh);
    conv_vt<<<dim3(SEQ / 32, HDIM / 32, 4 * NKVH), 256>>>(qkv, vt);

    // Flash attention (fp16 HMMA, cp.async K/V pipeline, 2 CTAs/SM)
    attn_h<<<dim3(SEQ / 128, NHEADS, TOKENS / SEQ), 256, ATT_SMEM>>>(qkh, vt, attnh);

    // Output projection (fp16 HMMA + ldmatrix)
    out_gemm<<<dim3(32, 32), 128, GSMEM>>>(attnh, wh, out);
}